// round 3
// baseline (speedup 1.0000x reference)
#include <cuda_runtime.h>
#include <math.h>

typedef unsigned long long ull;

namespace {
constexpr int B = 16, T = 100, N = 128, D = 3;
constexpr int FRAMES = B * T;                 // 1600
constexpr int FPB = 4;                        // frames per block (1 warp each)
constexpr int BLOCKS = FRAMES / FPB;          // 400
constexpr float MIN_DIST = 0.05f;
constexpr float R2 = MIN_DIST * MIN_DIST;     // 0.0025
constexpr float R2_GUARD = R2 + 1e-4f;        // slack for expansion error
constexpr int EXT = 208;                      // 128 + 80 wrap replica
}

__device__ float g_pen[FRAMES];
__device__ float g_work[FRAMES];
__device__ float g_stab[FRAMES];
__device__ float g_ke0[FRAMES];
__device__ float g_ke1[FRAMES];
__device__ unsigned int g_count;              // zero-init; self-resetting

// ---- packed f32x2 helpers (Blackwell FFMA2 path) ----
__device__ __forceinline__ ull pk2(float v) {
    ull r; asm("mov.b64 %0, {%1,%1};" : "=l"(r) : "f"(v)); return r;
}
__device__ __forceinline__ void upk(ull v, float& lo, float& hi) {
    asm("mov.b64 {%0,%1}, %2;" : "=f"(lo), "=f"(hi) : "l"(v));
}
__device__ __forceinline__ ull f2add(ull a, ull b) {
    ull r; asm("add.rn.f32x2 %0, %1, %2;" : "=l"(r) : "l"(a), "l"(b)); return r;
}
__device__ __forceinline__ ull f2fma(ull a, ull b, ull c) {
    ull r; asm("fma.rn.f32x2 %0, %1, %2, %3;" : "=l"(r) : "l"(a), "l"(b), "l"(c)); return r;
}

__global__ __launch_bounds__(128) void fused_kernel(
    const float* __restrict__ traj,
    const float* __restrict__ vel,
    const float* __restrict__ frc,
    float* __restrict__ out)
{
    const int tid = threadIdx.x;
    const int h   = tid >> 5;          // warp = frame slot 0..3
    const int u   = tid & 31;          // lane = row-quad index
    const int f   = blockIdx.x * FPB + h;
    const int t   = f % T;

    __shared__ __align__(16) float sx[FPB][EXT], sy[FPB][EXT],
                                   sz[FPB][EXT], sw[FPB][EXT];

    const float* pt = traj + (size_t)f * (N * D);

    // ---- load positions (SoA scatter) ----
    #pragma unroll
    for (int q = u; q < N * D; q += 32) {
        int p = q / 3, e = q - 3 * p;
        float v = pt[q];
        float* dst = (e == 0) ? &sx[h][p] : (e == 1) ? &sy[h][p] : &sz[h][p];
        *dst = v;
    }
    __syncwarp();
    #pragma unroll
    for (int p = u; p < N; p += 32) {
        float X = sx[h][p], Y = sy[h][p], Z = sz[h][p];
        sw[h][p] = X * X + Y * Y + Z * Z;
    }
    __syncwarp();
    // wrap replica: points 0..79 -> 128..207
    {
        int p = u;
        sx[h][128 + p] = sx[h][p]; sy[h][128 + p] = sy[h][p];
        sz[h][128 + p] = sz[h][p]; sw[h][128 + p] = sw[h][p];
        p = u + 32;
        sx[h][128 + p] = sx[h][p]; sy[h][128 + p] = sy[h][p];
        sz[h][128 + p] = sz[h][p]; sw[h][128 + p] = sw[h][p];
        if (u < 16) {
            p = u + 64;
            sx[h][128 + p] = sx[h][p]; sy[h][128 + p] = sy[h][p];
            sz[h][128 + p] = sz[h][p]; sw[h][128 + p] = sw[h][p];
        }
    }
    __syncwarp();

    const float* X = sx[h];
    const float* Y = sy[h];
    const float* Z = sz[h];
    const float* W = sw[h];

    // ---- per-thread 4 rows: r = 4u + rr ----
    const int r0 = 4 * u;
    ull wpk[4], mxp[4], myp[4], mzp[4];
    #pragma unroll
    for (int rr = 0; rr < 4; ++rr) {
        int r = r0 + rr;
        wpk[rr] = pk2(W[r]);
        mxp[rr] = pk2(-2.0f * X[r]);
        myp[rr] = pk2(-2.0f * Y[r]);
        mzp[rr] = pk2(-2.0f * Z[r]);
    }

    // ---- branch-free detection: min of expansion-d2 over superset of owned pairs
    float acc = 1e30f;
    {
        // j = 0: cols (r0, r0+1). self lanes: row0@lo, row1@hi.
        ull x2 = *(const ull*)&X[r0], y2 = *(const ull*)&Y[r0];
        ull z2 = *(const ull*)&Z[r0], w2 = *(const ull*)&W[r0];
        float lo, hi;
        ull d2;
        d2 = f2fma(mzp[0], z2, f2fma(myp[0], y2, f2fma(mxp[0], x2, f2add(wpk[0], w2))));
        upk(d2, lo, hi); acc = fminf(acc, hi);
        d2 = f2fma(mzp[1], z2, f2fma(myp[1], y2, f2fma(mxp[1], x2, f2add(wpk[1], w2))));
        upk(d2, lo, hi); acc = fminf(acc, lo);
        d2 = f2fma(mzp[2], z2, f2fma(myp[2], y2, f2fma(mxp[2], x2, f2add(wpk[2], w2))));
        upk(d2, lo, hi); acc = fminf(acc, fminf(lo, hi));
        d2 = f2fma(mzp[3], z2, f2fma(myp[3], y2, f2fma(mxp[3], x2, f2add(wpk[3], w2))));
        upk(d2, lo, hi); acc = fminf(acc, fminf(lo, hi));
        // j = 1: cols (r0+2, r0+3). self lanes: row2@lo, row3@hi.
        x2 = *(const ull*)&X[r0 + 2]; y2 = *(const ull*)&Y[r0 + 2];
        z2 = *(const ull*)&Z[r0 + 2]; w2 = *(const ull*)&W[r0 + 2];
        d2 = f2fma(mzp[0], z2, f2fma(myp[0], y2, f2fma(mxp[0], x2, f2add(wpk[0], w2))));
        upk(d2, lo, hi); acc = fminf(acc, fminf(lo, hi));
        d2 = f2fma(mzp[1], z2, f2fma(myp[1], y2, f2fma(mxp[1], x2, f2add(wpk[1], w2))));
        upk(d2, lo, hi); acc = fminf(acc, fminf(lo, hi));
        d2 = f2fma(mzp[2], z2, f2fma(myp[2], y2, f2fma(mxp[2], x2, f2add(wpk[2], w2))));
        upk(d2, lo, hi); acc = fminf(acc, hi);
        d2 = f2fma(mzp[3], z2, f2fma(myp[3], y2, f2fma(mxp[3], x2, f2add(wpk[3], w2))));
        upk(d2, lo, hi); acc = fminf(acc, lo);
    }
    #pragma unroll 11
    for (int j = 2; j < 35; ++j) {          // cols r0+4 .. r0+69
        int c = r0 + 2 * j;
        ull x2 = *(const ull*)&X[c], y2 = *(const ull*)&Y[c];
        ull z2 = *(const ull*)&Z[c], w2 = *(const ull*)&W[c];
        #pragma unroll
        for (int rr = 0; rr < 4; ++rr) {
            ull d2 = f2fma(mzp[rr], z2,
                     f2fma(myp[rr], y2,
                     f2fma(mxp[rr], x2, f2add(wpk[rr], w2))));
            float lo, hi; upk(d2, lo, hi);
            acc = fminf(acc, fminf(lo, hi));
        }
    }

    // ---- rare exact slow path (ownership: row r owns j=1..63 full, j=64 half)
    float pen = 0.f;
    if (acc < R2_GUARD) {
        #pragma unroll
        for (int rr = 0; rr < 4; ++rr) {
            int r = r0 + rr;
            float px = X[r], py = Y[r], pz = Z[r];
            for (int j = 1; j <= 64; ++j) {
                int k = r + j;
                float dx = px - X[k], dy = py - Y[k], dz = pz - Z[k];
                float e2 = dx * dx + dy * dy + dz * dz;
                if (e2 < R2) {
                    float c = MIN_DIST - sqrtf(e2);
                    pen += (j == 64) ? 0.5f * c : c;
                }
            }
        }
    }

    // ---- energy work term ----
    float wrk = 0.f;
    if (t < T - 1) {
        const float* pf = frc + (size_t)f * (N * D);
        const float* p1 = pt + N * D;
        #pragma unroll
        for (int q = u; q < N * D; q += 32)
            wrk += pf[q] * (p1[q] - pt[q]);
    }

    // ---- stability / kinetic ----
    float stab = 0.f, ke = 0.f;
    if (t >= T - 5) {
        const float* pv = vel + (size_t)f * (N * D);
        #pragma unroll
        for (int p = u; p < N; p += 32) {
            float vx = pv[3 * p], vy = pv[3 * p + 1], vz = pv[3 * p + 2];
            float v2 = vx * vx + vy * vy + vz * vz;
            stab += sqrtf(v2);
            if (t == T - 1) ke += 0.5f * v2;
        }
    } else if (t == 0) {
        const float* pv = vel + (size_t)f * (N * D);
        #pragma unroll
        for (int q = u; q < N * D; q += 32) {
            float v = pv[q]; ke += 0.5f * v * v;
        }
    }

    // ---- single-warp reduction per frame ----
    #pragma unroll
    for (int off = 16; off > 0; off >>= 1) {
        pen  += __shfl_down_sync(0xffffffffu, pen,  off);
        wrk  += __shfl_down_sync(0xffffffffu, wrk,  off);
        stab += __shfl_down_sync(0xffffffffu, stab, off);
        ke   += __shfl_down_sync(0xffffffffu, ke,   off);
    }
    if (u == 0) {
        g_pen[f]  = pen;
        g_work[f] = wrk;
        g_stab[f] = stab;
        g_ke0[f]  = (t == 0)     ? ke : 0.f;
        g_ke1[f]  = (t == T - 1) ? ke : 0.f;
    }

    // ---- last-arriving block: deterministic final reduction ----
    __threadfence();
    __syncthreads();
    __shared__ int is_last;
    if (tid == 0) {
        unsigned int old = atomicAdd(&g_count, 1u);
        is_last = (old == BLOCKS - 1) ? 1 : 0;
    }
    __syncthreads();
    if (!is_last) return;

    float pen_s = 0.f, wrk_s = 0.f, stab_s = 0.f, k0 = 0.f, k1 = 0.f;
    #pragma unroll 4
    for (int q = tid; q < FRAMES; q += 128) {
        pen_s  += g_pen[q];
        wrk_s  += g_work[q];
        stab_s += g_stab[q];
        k0     += g_ke0[q];
        k1     += g_ke1[q];
    }
    #pragma unroll
    for (int off = 16; off > 0; off >>= 1) {
        pen_s  += __shfl_down_sync(0xffffffffu, pen_s,  off);
        wrk_s  += __shfl_down_sync(0xffffffffu, wrk_s,  off);
        stab_s += __shfl_down_sync(0xffffffffu, stab_s, off);
        k0     += __shfl_down_sync(0xffffffffu, k0,     off);
        k1     += __shfl_down_sync(0xffffffffu, k1,     off);
    }
    __shared__ float sm[4][5];
    if (u == 0) {
        sm[h][0] = pen_s; sm[h][1] = wrk_s; sm[h][2] = stab_s;
        sm[h][3] = k0;    sm[h][4] = k1;
    }
    __syncthreads();
    if (tid == 0) {
        float sp = 0.f, swk = 0.f, ss = 0.f, s0 = 0.f, s1 = 0.f;
        #pragma unroll
        for (int wv = 0; wv < 4; ++wv) {
            sp += sm[wv][0]; swk += sm[wv][1]; ss += sm[wv][2];
            s0 += sm[wv][3]; s1  += sm[wv][4];
        }
        const float pen_loss  = sp / (float)B / ((float)T * (float)N * (float)(N - 1) * 0.5f);
        const float work_mean = swk / (float)(B * (T - 1) * N);
        const float stab_mean = ss / (float)(B * 5 * N);
        const float ks        = s0 / (float)(B * N);
        const float ke_       = s1 / (float)(B * N);
        out[0] = 10.0f * pen_loss + stab_mean + 0.1f * fabsf(ke_ - ks - work_mean);
        g_count = 0u;   // self-reset for next graph replay
    }
}

extern "C" void kernel_launch(void* const* d_in, const int* in_sizes, int n_in,
                              void* d_out, int out_size)
{
    const float* traj = (const float*)d_in[0];
    const float* vel  = (const float*)d_in[1];
    const float* frc  = (const float*)d_in[2];

    fused_kernel<<<BLOCKS, 128>>>(traj, vel, frc, (float*)d_out);
}

// round 4
// speedup vs baseline: 1.3226x; 1.3226x over previous
#include <cuda_runtime.h>
#include <math.h>

namespace {
constexpr int B = 16, T = 100, N = 128, D = 3;
constexpr int FRAMES = B * T;                 // 1600
constexpr float MIN_DIST = 0.05f;
constexpr float R2 = MIN_DIST * MIN_DIST;     // 0.0025
constexpr float R2_GUARD = R2 + 1e-4f;        // slack for expansion error
constexpr int EXT = 192;                      // 128 + 64 wrap replica
}

__device__ float g_pen[FRAMES];
__device__ float g_work[FRAMES];
__device__ float g_stab[FRAMES];
__device__ float g_ke0[FRAMES];
__device__ float g_ke1[FRAMES];
__device__ unsigned int g_count;              // zero-init; self-resetting

__global__ __launch_bounds__(256) void fused_kernel(
    const float* __restrict__ traj,
    const float* __restrict__ vel,
    const float* __restrict__ frc,
    float* __restrict__ out)
{
    const int tid  = threadIdx.x;
    const int i    = tid & 127;        // row index 0..127
    const int half = tid >> 7;         // 0: j=1..32, 1: j=33..64
    const int f    = blockIdx.x;       // one frame per block
    const int t    = f % T;

    __shared__ __align__(16) float4 spos[EXT];   // (x, y, z, |p|^2)

    const float* pt = traj + (size_t)f * (N * D);

    // ---- cooperative load of 384 floats into float4 slots ----
    float* sraw = reinterpret_cast<float*>(spos);
    {
        int q = tid;
        if (q < N * D) {
            int p = q / 3, e = q - 3 * p;
            sraw[4 * p + e] = pt[q];
        }
        q = tid + 256;
        if (q < N * D) {
            int p = q / 3, e = q - 3 * p;
            sraw[4 * p + e] = pt[q];
        }
    }
    __syncthreads();
    if (tid < N) {      // fill .w = |p|^2
        float4 v = spos[tid];
        spos[tid].w = v.x * v.x + v.y * v.y + v.z * v.z;
    }
    __syncthreads();
    if (tid < 64)       // wrap replica 0..63 -> 128..191
        spos[128 + tid] = spos[tid];
    __syncthreads();

    const float4 me = spos[i];
    const float mw  = me.w;
    const float m2x = -2.0f * me.x;
    const float m2y = -2.0f * me.y;
    const float m2z = -2.0f * me.z;

    // ---- detection pass: branch-free min(d2) over this thread's 32 columns
    const int jbase = 1 + 32 * half;
    const float4* base = spos + i + jbase;
    float accA = 1e30f, accB = 1e30f;
    #pragma unroll
    for (int jj = 0; jj < 32; ++jj) {
        float4 qq = base[jj];
        float d2 = mw + qq.w;
        d2 = fmaf(m2x, qq.x, d2);
        d2 = fmaf(m2y, qq.y, d2);
        d2 = fmaf(m2z, qq.z, d2);
        if (jj & 1) accB = fminf(accB, d2);
        else        accA = fminf(accA, d2);
    }

    // ---- rare exact slow path ----
    float pen = 0.f;
    if (fminf(accA, accB) < R2_GUARD) {
        for (int jj = 0; jj < 32; ++jj) {
            float4 qq = base[jj];
            float dx = me.x - qq.x, dy = me.y - qq.y, dz = me.z - qq.z;
            float e2 = dx * dx + dy * dy + dz * dz;
            if (e2 < R2) {
                float c = MIN_DIST - sqrtf(e2);
                // j == 64 pairs are enumerated from both endpoints -> half weight
                pen += (jbase + jj == 64) ? 0.5f * c : c;
            }
        }
    }

    // ---- energy work term (coalesced elementwise) ----
    float wrk = 0.f;
    if (t < T - 1) {
        const float* pf = frc + (size_t)f * (N * D);
        const float* p1 = pt + N * D;
        if (tid < N * D)       wrk += pf[tid]       * (p1[tid]       - pt[tid]);
        if (tid + 256 < N * D) wrk += pf[tid + 256] * (p1[tid + 256] - pt[tid + 256]);
    }

    // ---- stability / kinetic (first 128 threads, one point each) ----
    float stab = 0.f, ke = 0.f;
    if (half == 0) {
        if (t >= T - 5) {
            const float* pv = vel + (size_t)f * (N * D);
            float vx = pv[3 * i], vy = pv[3 * i + 1], vz = pv[3 * i + 2];
            float v2 = vx * vx + vy * vy + vz * vz;
            stab = sqrtf(v2);
            if (t == T - 1) ke = 0.5f * v2;
        } else if (t == 0) {
            const float* pv = vel + (size_t)f * (N * D);
            float vx = pv[3 * i], vy = pv[3 * i + 1], vz = pv[3 * i + 2];
            ke = 0.5f * (vx * vx + vy * vy + vz * vz);
        }
    }

    // ---- block reduction of (pen, wrk, stab, ke) ----
    float4 acc4 = make_float4(pen, wrk, stab, ke);
    #pragma unroll
    for (int off = 16; off > 0; off >>= 1) {
        acc4.x += __shfl_down_sync(0xffffffffu, acc4.x, off);
        acc4.y += __shfl_down_sync(0xffffffffu, acc4.y, off);
        acc4.z += __shfl_down_sync(0xffffffffu, acc4.z, off);
        acc4.w += __shfl_down_sync(0xffffffffu, acc4.w, off);
    }
    __shared__ float4 wsum[8];
    if ((tid & 31) == 0) wsum[tid >> 5] = acc4;
    __syncthreads();
    if (tid == 0) {
        float4 s = wsum[0];
        #pragma unroll
        for (int w = 1; w < 8; ++w) {
            s.x += wsum[w].x; s.y += wsum[w].y;
            s.z += wsum[w].z; s.w += wsum[w].w;
        }
        g_pen[f]  = s.x;
        g_work[f] = s.y;
        g_stab[f] = s.z;
        g_ke0[f]  = (t == 0)     ? s.w : 0.f;
        g_ke1[f]  = (t == T - 1) ? s.w : 0.f;
    }

    // ---- last-arriving block: deterministic final reduction ----
    __threadfence();
    __shared__ int is_last;
    if (tid == 0) {
        unsigned int old = atomicAdd(&g_count, 1u);
        is_last = (old == FRAMES - 1) ? 1 : 0;
    }
    __syncthreads();
    if (!is_last) return;

    float pen_s = 0.f, wrk_s = 0.f, stab_s = 0.f, k0 = 0.f, k1 = 0.f;
    #pragma unroll 4
    for (int q = tid; q < FRAMES; q += 256) {
        pen_s  += g_pen[q];
        wrk_s  += g_work[q];
        stab_s += g_stab[q];
        k0     += g_ke0[q];
        k1     += g_ke1[q];
    }
    #pragma unroll
    for (int off = 16; off > 0; off >>= 1) {
        pen_s  += __shfl_down_sync(0xffffffffu, pen_s,  off);
        wrk_s  += __shfl_down_sync(0xffffffffu, wrk_s,  off);
        stab_s += __shfl_down_sync(0xffffffffu, stab_s, off);
        k0     += __shfl_down_sync(0xffffffffu, k0,     off);
        k1     += __shfl_down_sync(0xffffffffu, k1,     off);
    }
    __shared__ float sm[8][5];
    if ((tid & 31) == 0) {
        int w = tid >> 5;
        sm[w][0] = pen_s; sm[w][1] = wrk_s; sm[w][2] = stab_s;
        sm[w][3] = k0;    sm[w][4] = k1;
    }
    __syncthreads();
    if (tid == 0) {
        float sp = 0.f, swk = 0.f, ss = 0.f, s0 = 0.f, s1 = 0.f;
        #pragma unroll
        for (int wv = 0; wv < 8; ++wv) {
            sp += sm[wv][0]; swk += sm[wv][1]; ss += sm[wv][2];
            s0 += sm[wv][3]; s1  += sm[wv][4];
        }
        const float pen_loss  = sp / (float)B / ((float)T * (float)N * (float)(N - 1) * 0.5f);
        const float work_mean = swk / (float)(B * (T - 1) * N);
        const float stab_mean = ss / (float)(B * 5 * N);
        const float ks        = s0 / (float)(B * N);
        const float ke_       = s1 / (float)(B * N);
        out[0] = 10.0f * pen_loss + stab_mean + 0.1f * fabsf(ke_ - ks - work_mean);
        g_count = 0u;   // self-reset for next graph replay
    }
}

extern "C" void kernel_launch(void* const* d_in, const int* in_sizes, int n_in,
                              void* d_out, int out_size)
{
    const float* traj = (const float*)d_in[0];
    const float* vel  = (const float*)d_in[1];
    const float* frc  = (const float*)d_in[2];

    fused_kernel<<<FRAMES, 256>>>(traj, vel, frc, (float*)d_out);
}

// round 5
// speedup vs baseline: 1.3249x; 1.0017x over previous
#include <cuda_runtime.h>
#include <math.h>

namespace {
constexpr int B = 16, T = 100, N = 128, D = 3;
constexpr int FRAMES = B * T;                 // 1600
constexpr int FPB = 2;                        // frames per block
constexpr int BLOCKS = FRAMES / FPB;          // 800
constexpr float MIN_DIST = 0.05f;
constexpr float R2 = MIN_DIST * MIN_DIST;     // 0.0025
constexpr float R2_GUARD = R2 + 1e-4f;        // slack for expansion error
constexpr int EXT = 192;                      // 128 + 64 wrap replica
}

__device__ float g_pen[FRAMES];
__device__ float g_work[FRAMES];
__device__ float g_stab[FRAMES];
__device__ float g_ke0[FRAMES];
__device__ float g_ke1[FRAMES];
__device__ unsigned int g_count;              // zero-init; self-resetting

__global__ __launch_bounds__(256, 6) void fused_kernel(
    const float* __restrict__ traj,
    const float* __restrict__ vel,
    const float* __restrict__ frc,
    float* __restrict__ out)
{
    const int tid = threadIdx.x;
    const int u   = tid & 127;         // within-frame thread
    const int fh  = tid >> 7;          // frame slot in block (0/1)
    const int f   = blockIdx.x * FPB + fh;
    const int t   = f % T;
    const int m   = u & 63;            // row-pair index
    const int h   = u >> 6;            // j-half: 0 -> j=1..32, 1 -> j=33..64

    __shared__ __align__(16) float4 spos[FPB][EXT];   // (x,y,z,|p|^2)

    const float* pt = traj + (size_t)f * (N * D);

    // ---- cooperative load of this frame's 384 floats into float4 slots ----
    float* sraw = reinterpret_cast<float*>(spos[fh]);
    #pragma unroll
    for (int q = u; q < N * D; q += 128) {
        int p = q / 3, e = q - 3 * p;
        sraw[4 * p + e] = pt[q];
    }
    __syncthreads();
    {   // fill .w = |p|^2
        float4 v = spos[fh][u];
        spos[fh][u].w = v.x * v.x + v.y * v.y + v.z * v.z;
    }
    __syncthreads();
    if (u < 64)     // wrap replica 0..63 -> 128..191
        spos[fh][128 + u] = spos[fh][u];
    __syncthreads();

    const float4* P = spos[fh];
    const int r0 = 2 * m;

    const float4 A  = P[r0];
    const float4 Bv = P[r0 + 1];
    const float w0 = A.w,  ax = -2.0f * A.x,  ay = -2.0f * A.y,  az = -2.0f * A.z;
    const float w1 = Bv.w, bx = -2.0f * Bv.x, by = -2.0f * Bv.y, bz = -2.0f * Bv.z;

    const int jb = 1 + 32 * h;          // first owned j
    const int c0 = r0 + jb;             // first column

    // ---- detection: branch-free min(d2) over owned pairs, cols shared by 2 rows
    float acc0 = 1e30f, acc1 = 1e30f, acc2 = 1e30f, acc3 = 1e30f;
    {   // k = 0: row0 only (row1 would be j = jb-1, possibly self-pair)
        float4 q = P[c0];
        float s = w0 + q.w;
        s = fmaf(ax, q.x, s); s = fmaf(ay, q.y, s); s = fmaf(az, q.z, s);
        acc0 = s;
    }
    #pragma unroll
    for (int k = 1; k < 32; ++k) {      // both rows
        float4 q = P[c0 + k];
        float s0 = w0 + q.w;
        s0 = fmaf(ax, q.x, s0); s0 = fmaf(ay, q.y, s0); s0 = fmaf(az, q.z, s0);
        float s1 = w1 + q.w;
        s1 = fmaf(bx, q.x, s1); s1 = fmaf(by, q.y, s1); s1 = fmaf(bz, q.z, s1);
        if (k & 1) { acc1 = fminf(acc1, s0); acc3 = fminf(acc3, s1); }
        else       { acc0 = fminf(acc0, s0); acc2 = fminf(acc2, s1); }
    }
    {   // k = 32: row1 only (j = jb+31)
        float4 q = P[c0 + 32];
        float s1 = w1 + q.w;
        s1 = fmaf(bx, q.x, s1); s1 = fmaf(by, q.y, s1); s1 = fmaf(bz, q.z, s1);
        acc2 = fminf(acc2, s1);
    }
    const float dmin = fminf(fminf(acc0, acc1), fminf(acc2, acc3));

    // ---- rare exact slow path over owned pairs ----
    float pen = 0.f;
    if (dmin < R2_GUARD) {
        #pragma unroll
        for (int rr = 0; rr < 2; ++rr) {
            const int r = r0 + rr;
            const float px = P[r].x, py = P[r].y, pz = P[r].z;
            #pragma unroll 4
            for (int kk = 0; kk < 32; ++kk) {
                const int j = jb + kk;
                const int k = r + j;
                float dx = px - P[k].x, dy = py - P[k].y, dz = pz - P[k].z;
                float e2 = dx * dx + dy * dy + dz * dz;
                if (e2 < R2) {
                    float c = MIN_DIST - sqrtf(e2);
                    pen += (j == 64) ? 0.5f * c : c;   // j=64 counted from both ends
                }
            }
        }
    }

    // ---- energy work term (coalesced elementwise per frame) ----
    float wrk = 0.f;
    if (t < T - 1) {
        const float* pf = frc + (size_t)f * (N * D);
        const float* p1 = pt + N * D;
        #pragma unroll
        for (int q = u; q < N * D; q += 128)
            wrk += pf[q] * (p1[q] - pt[q]);
    }

    // ---- stability / kinetic (boundary frames only) ----
    float stab = 0.f, ke = 0.f;
    if (t >= T - 5) {
        const float* pv = vel + (size_t)f * (N * D);
        float vx = pv[3 * u], vy = pv[3 * u + 1], vz = pv[3 * u + 2];
        float v2 = vx * vx + vy * vy + vz * vz;
        stab = sqrtf(v2);
        if (t == T - 1) ke = 0.5f * v2;
    } else if (t == 0) {
        const float* pv = vel + (size_t)f * (N * D);
        float vx = pv[3 * u], vy = pv[3 * u + 1], vz = pv[3 * u + 2];
        ke = 0.5f * (vx * vx + vy * vy + vz * vz);
    }

    // ---- per-frame reduction (4 warps each) ----
    float4 acc4 = make_float4(pen, wrk, stab, ke);
    #pragma unroll
    for (int off = 16; off > 0; off >>= 1) {
        acc4.x += __shfl_down_sync(0xffffffffu, acc4.x, off);
        acc4.y += __shfl_down_sync(0xffffffffu, acc4.y, off);
        acc4.z += __shfl_down_sync(0xffffffffu, acc4.z, off);
        acc4.w += __shfl_down_sync(0xffffffffu, acc4.w, off);
    }
    __shared__ float4 wsum[8];
    if ((tid & 31) == 0) wsum[tid >> 5] = acc4;
    __syncthreads();
    if (u == 0) {                       // tid 0 (frame 0) and tid 128 (frame 1)
        float4 s = wsum[4 * fh];
        #pragma unroll
        for (int w = 1; w < 4; ++w) {
            s.x += wsum[4 * fh + w].x; s.y += wsum[4 * fh + w].y;
            s.z += wsum[4 * fh + w].z; s.w += wsum[4 * fh + w].w;
        }
        g_pen[f]  = s.x;
        g_work[f] = s.y;
        g_stab[f] = s.z;
        g_ke0[f]  = (t == 0)     ? s.w : 0.f;
        g_ke1[f]  = (t == T - 1) ? s.w : 0.f;
    }

    // ---- last-arriving block: deterministic final reduction ----
    __threadfence();
    __shared__ int is_last;
    if (tid == 0) {
        unsigned int old = atomicAdd(&g_count, 1u);
        is_last = (old == BLOCKS - 1) ? 1 : 0;
    }
    __syncthreads();
    if (!is_last) return;

    float pen_s = 0.f, wrk_s = 0.f, stab_s = 0.f, k0 = 0.f, k1 = 0.f;
    #pragma unroll 4
    for (int q = tid; q < FRAMES; q += 256) {
        pen_s  += g_pen[q];
        wrk_s  += g_work[q];
        stab_s += g_stab[q];
        k0     += g_ke0[q];
        k1     += g_ke1[q];
    }
    #pragma unroll
    for (int off = 16; off > 0; off >>= 1) {
        pen_s  += __shfl_down_sync(0xffffffffu, pen_s,  off);
        wrk_s  += __shfl_down_sync(0xffffffffu, wrk_s,  off);
        stab_s += __shfl_down_sync(0xffffffffu, stab_s, off);
        k0     += __shfl_down_sync(0xffffffffu, k0,     off);
        k1     += __shfl_down_sync(0xffffffffu, k1,     off);
    }
    __shared__ float sm[8][5];
    if ((tid & 31) == 0) {
        int w = tid >> 5;
        sm[w][0] = pen_s; sm[w][1] = wrk_s; sm[w][2] = stab_s;
        sm[w][3] = k0;    sm[w][4] = k1;
    }
    __syncthreads();
    if (tid == 0) {
        float sp = 0.f, swk = 0.f, ss = 0.f, s0 = 0.f, s1 = 0.f;
        #pragma unroll
        for (int wv = 0; wv < 8; ++wv) {
            sp += sm[wv][0]; swk += sm[wv][1]; ss += sm[wv][2];
            s0 += sm[wv][3]; s1  += sm[wv][4];
        }
        const float pen_loss  = sp / (float)B / ((float)T * (float)N * (float)(N - 1) * 0.5f);
        const float work_mean = swk / (float)(B * (T - 1) * N);
        const float stab_mean = ss / (float)(B * 5 * N);
        const float ks        = s0 / (float)(B * N);
        const float ke_       = s1 / (float)(B * N);
        out[0] = 10.0f * pen_loss + stab_mean + 0.1f * fabsf(ke_ - ks - work_mean);
        g_count = 0u;   // self-reset for next graph replay
    }
}

extern "C" void kernel_launch(void* const* d_in, const int* in_sizes, int n_in,
                              void* d_out, int out_size)
{
    const float* traj = (const float*)d_in[0];
    const float* vel  = (const float*)d_in[1];
    const float* frc  = (const float*)d_in[2];

    fused_kernel<<<BLOCKS, 256>>>(traj, vel, frc, (float*)d_out);
}